// round 6
// baseline (speedup 1.0000x reference)
#include <cuda_runtime.h>
#include <cstdint>
#include <math_constants.h>

#define NB 16
#define NA 65472
#define NC 81
#define NG 50
#define NSLICE 8
#define BETA_C (1.0f/9.0f)
#define CHUNK 64                      // anchors per pipeline chunk
#define CPB 3                         // chunks per block; 1023 = 341*3
#define CHUNK_FLOATS (CHUNK*NC)       // 5184 floats = 20736 B
#define CHUNK_VEC (CHUNK_FLOATS/4)    // 1296 float4

// ---------------- scratch (static __device__, no allocation) ----------------
__device__ float              g_bestIou[NB][NA];
__device__ unsigned char      g_bestIdx[NB][NA];
__device__ unsigned long long g_gtBest[NB][NG];
__device__ unsigned           g_mining[NB][NA];     // float bits; sign bit => positive anchor
__device__ unsigned           g_h0cnt[NB][NSLICE][2048];
__device__ float              g_h0sum[NB][NSLICE][2048];
__device__ int                g_numPosB[NB];
__device__ float              g_posCe;
__device__ float              g_locSum;
__device__ float              g_negSum[NB];

// ---------------- zero scratch (graph replays re-run this) ----------------
__global__ void k_zero() {
    int i = blockIdx.x * blockDim.x + threadIdx.x;   // 0 .. 262143
    ((unsigned*)g_h0cnt)[i] = 0u;
    ((float*)g_h0sum)[i]    = 0.f;
    if (i < NB * NG)   ((unsigned long long*)g_gtBest)[i] = 0ull;
    if (i < NB)        { g_numPosB[i] = 0; g_negSum[i] = 0.f; }
    if (i == 0)        { g_posCe = 0.f; g_locSum = 0.f; }
}

// ---------------- matching: per-anchor best box + per-GT best anchor ----------------
__global__ __launch_bounds__(256) void k_match(
    const float* __restrict__ gts, const int* __restrict__ counts,
    const float* __restrict__ anchors)
{
    __shared__ float sbx0[NG], sby0[NG], sbx1[NG], sby1[NG], sba[NG];
    __shared__ unsigned long long sgt[NG];
    int b = blockIdx.y;
    int tid = threadIdx.x;
    if (tid < NG) {
        const float* g = gts + ((size_t)b * NG + tid) * 5;
        float x0 = g[0], y0 = g[1], x1 = g[2], y1 = g[3];
        sbx0[tid] = x0; sby0[tid] = y0; sbx1[tid] = x1; sby1[tid] = y1;
        sba[tid]  = (x1 - x0) * (y1 - y0);
        sgt[tid]  = 0ull;
    }
    __syncthreads();
    int count = counts[b];
    int a = blockIdx.x * blockDim.x + tid;
    bool valid = a < NA;
    float ax0 = 0, ay0 = 0, ax1 = 0, ay1 = 0, aarea = 0;
    if (valid) {
        const float* ap = anchors + (size_t)a * 4;
        ax0 = ap[0]; ay0 = ap[1]; ax1 = ap[2]; ay1 = ap[3];
        aarea = (ax1 - ax0) * (ay1 - ay0);
    }
    float best = -1.f; int bidx = 0;
    int lane = tid & 31;
    for (int g = 0; g < count; ++g) {
        float ltx = fmaxf(ax0, sbx0[g]), lty = fmaxf(ay0, sby0[g]);
        float rbx = fminf(ax1, sbx1[g]), rby = fminf(ay1, sby1[g]);
        float w = fmaxf(rbx - ltx, 0.f), h = fmaxf(rby - lty, 0.f);
        float inter = w * h;
        unsigned key = 0u;
        if (valid && inter > 0.f) {
            float iou = __fdividef(inter, aarea + sba[g] - inter + 1e-10f);
            if (iou > best) { best = iou; bidx = g; }
            key = __float_as_uint(iou);
        }
        unsigned wmax = __reduce_max_sync(0xffffffffu, key);
        if (wmax) {
            unsigned ball = __ballot_sync(0xffffffffu, key == wmax);
            if (lane == (__ffs(ball) - 1))
                atomicMax(&sgt[g], ((unsigned long long)wmax << 32) |
                                   (unsigned long long)(0xFFFFFFFFu - (unsigned)a));
        }
    }
    if (valid) {
        g_bestIou[b][a] = best;
        g_bestIdx[b][a] = (unsigned char)bidx;
    }
    __syncthreads();
    if (tid < count) atomicMax(&g_gtBest[b][tid], sgt[tid]);
}

// ---------------- forced scatter: each GT's best anchor becomes positive ----------------
__global__ void k_scatter(const int* __restrict__ counts) {
    int b = threadIdx.x;
    if (b >= NB) return;
    int count = counts[b];
    for (int g = 0; g < count; ++g) {   // ascending: last g wins on collision
        unsigned long long p = g_gtBest[b][g];
        unsigned a = p ? (0xFFFFFFFFu - (unsigned)(p & 0xFFFFFFFFull)) : 0u;
        g_bestIou[b][a] = 2.0f;
        g_bestIdx[b][a] = (unsigned char)g;
    }
}

// ---------------- main streaming pass: pipelined cp.async, 4 threads/anchor ----------------
__global__ __launch_bounds__(256) void k_main(
    const float* __restrict__ conf, const float* __restrict__ pred,
    const float* __restrict__ gts,  const float* __restrict__ anchors)
{
    __shared__ float sm[2][CHUNK_FLOATS];            // 2 * 20736 B
    __shared__ float s_posCe, s_loc;
    __shared__ int   s_np;
    int b = blockIdx.y;
    int t = threadIdx.x;
    int al = t >> 2, p = t & 3;                      // anchor-in-chunk, class partition
    if (t == 0) { s_posCe = 0.f; s_loc = 0.f; s_np = 0; }

    int chunk0 = blockIdx.x * CPB;
    const float* base = conf + (size_t)b * NA * NC;
    unsigned sbase = (unsigned)__cvta_generic_to_shared(&sm[0][0]);

    // preload chunk0 -> buf0
    {
        const float4* src = (const float4*)(base + (size_t)chunk0 * CHUNK_FLOATS);
        for (int j = t; j < CHUNK_VEC; j += 256)
            asm volatile("cp.async.cg.shared.global [%0], [%1], 16;"
                         :: "r"(sbase + j * 16), "l"(src + j));
        asm volatile("cp.async.commit_group;");
    }

    for (int i = 0; i < CPB; ++i) {
        int cur = i & 1;
        if (i + 1 < CPB) {
            const float4* src = (const float4*)(base + (size_t)(chunk0 + i + 1) * CHUNK_FLOATS);
            unsigned dst = sbase + (cur ^ 1) * (CHUNK_FLOATS * 4);
            for (int j = t; j < CHUNK_VEC; j += 256)
                asm volatile("cp.async.cg.shared.global [%0], [%1], 16;"
                             :: "r"(dst + j * 16), "l"(src + j));
            asm volatile("cp.async.commit_group;");
            asm volatile("cp.async.wait_group 1;");
        } else {
            asm volatile("cp.async.wait_group 0;");
        }
        __syncthreads();

        int c = chunk0 + i;
        const float* row = &sm[cur][al * NC];
        float x0 = 0.f, s = 0.f, s1 = 0.f;
        if (p == 0) { x0 = row[0]; s = __expf(x0); }
        const float* q = row + 1 + p * 20;
        #pragma unroll
        for (int j = 0; j < 20; j += 2) { s += __expf(q[j]); s1 += __expf(q[j + 1]); }
        s += s1;
        s += __shfl_xor_sync(0xffffffffu, s, 1);
        s += __shfl_xor_sync(0xffffffffu, s, 2);

        if (p == 0) {
            float lse = __logf(s);
            int a = c * CHUNK + al;
            float iou = g_bestIou[b][a];
            int   gi  = g_bestIdx[b][a];
            int label = 0;
            if (iou >= 0.5f) label = (int)gts[((size_t)b * NG + gi) * 5 + 4];
            if (label > 0) {
                float ce = lse - row[label];
                g_mining[b][a] = 0x80000000u;
                atomicAdd(&s_posCe, ce);
                atomicAdd(&s_np, 1);
                const float* gb = gts + ((size_t)b * NG + gi) * 5;
                float bx0 = gb[0], by0 = gb[1], bx1 = gb[2], by1 = gb[3];
                const float* ap = anchors + (size_t)a * 4;
                float ax0 = ap[0], ay0 = ap[1], ax1 = ap[2], ay1 = ap[3];
                float acx = (ax0 + ax1) * 0.5f, acy = (ay0 + ay1) * 0.5f;
                float aw = ax1 - ax0, ah = ay1 - ay0;
                float mcx = (bx0 + bx1) * 0.5f, mcy = (by0 + by1) * 0.5f;
                float mw = bx1 - bx0, mh = by1 - by0;
                float tt[4];
                tt[0] = (mcx - acx) / (aw * 0.1f);
                tt[1] = (mcy - acy) / (ah * 0.1f);
                tt[2] = logf(mw / aw + 1e-10f) / 0.2f;
                tt[3] = logf(mh / ah + 1e-10f) / 0.2f;
                const float* pp = pred + ((size_t)b * NA + a) * 4;
                float ls = 0.f;
                #pragma unroll
                for (int j = 0; j < 4; j++) {
                    float n = fabsf(pp[j] - tt[j]);
                    ls += (n < BETA_C) ? 0.5f * n * n * (1.f / BETA_C) : n - 0.5f * BETA_C;
                }
                atomicAdd(&s_loc, ls);
            } else {
                float mining = lse - x0;                 // = ce for class 0; > 0
                unsigned bits = __float_as_uint(mining);
                g_mining[b][a] = bits;
                int slice = (c ^ al) & (NSLICE - 1);
                atomicAdd(&g_h0cnt[b][slice][bits >> 20], 1u);
                atomicAdd(&g_h0sum[b][slice][bits >> 20], mining);
            }
        }
        __syncthreads();   // buffer `cur` may be overwritten next iteration
    }
    if (t == 0) {
        if (s_np)            atomicAdd(&g_numPosB[b], s_np);
        if (s_posCe != 0.f)  atomicAdd(&g_posCe, s_posCe);
        if (s_loc   != 0.f)  atomicAdd(&g_locSum, s_loc);
    }
}

// ---------------- block-wide radix-bin threshold finder ----------------
__device__ void block_select(const unsigned* cnt, const float* sum, int nbins, int k,
                             int& bin, int& krem, float& above, int& all)
{
    __shared__ unsigned sc[256];
    __shared__ float ss[256];
    __shared__ int rbin, rkrem, rall;
    __shared__ float rabove;
    int t = threadIdx.x;
    int per = nbins >> 8;
    int lo = t * per;
    unsigned ccnt = 0; float csum = 0.f;
    for (int i = 0; i < per; i++) { ccnt += cnt[lo + i]; csum += sum[lo + i]; }
    sc[t] = ccnt; ss[t] = csum;
    __syncthreads();
    for (int off = 1; off < 256; off <<= 1) {            // inclusive suffix scan
        unsigned cv = (t + off < 256) ? sc[t + off] : 0u;
        float sv    = (t + off < 256) ? ss[t + off] : 0.f;
        __syncthreads();
        sc[t] += cv; ss[t] += sv;
        __syncthreads();
    }
    if (t == 0) { rall = (sc[0] <= (unsigned)k); rabove = ss[0]; rbin = -1; rkrem = 0; }
    __syncthreads();
    if (!rall) {
        unsigned cabove = sc[t] - ccnt;                  // strictly above this chunk
        if (cabove <= (unsigned)k && cabove + ccnt > (unsigned)k) {
            unsigned run = cabove;
            float srun = ss[t] - csum;
            for (int bb = lo + per - 1; bb >= lo; --bb) {
                unsigned cb = cnt[bb];
                if (run + cb > (unsigned)k) { rbin = bb; rkrem = k - (int)run; rabove = srun; break; }
                run += cb; srun += sum[bb];
            }
        }
    }
    __syncthreads();
    bin = rbin; krem = rkrem; above = rabove; all = rall;
}

// ---------------- fused negative-mining selection: one block per batch ----------------
__global__ __launch_bounds__(256) void k_neg() {
    __shared__ unsigned h1c[4096];
    __shared__ float    h1s[4096];
    __shared__ unsigned h2c[256];
    __shared__ float    h2s[256];
    int b = blockIdx.x;
    int t = threadIdx.x;

    // collapse h0 slices into slice 0
    for (int bin = t; bin < 2048; bin += 256) {
        unsigned c = 0; float s = 0.f;
        #pragma unroll
        for (int sl = 0; sl < NSLICE; ++sl) { c += g_h0cnt[b][sl][bin]; s += g_h0sum[b][sl][bin]; }
        g_h0cnt[b][0][bin] = c; g_h0sum[b][0][bin] = s;
    }
    __syncthreads();

    int k = 3 * g_numPosB[b];
    int bin0, krem0, all0; float above0;
    block_select(&g_h0cnt[b][0][0], &g_h0sum[b][0][0], 2048, k, bin0, krem0, above0, all0);
    if (k == 0) return;                                   // negSum stays 0
    if (all0) { if (t == 0) g_negSum[b] = above0; return; }
    float acc = above0;

    // pass 1: refine within bin0 on mantissa bits [19:8]
    for (int i = t; i < 4096; i += 256) { h1c[i] = 0u; h1s[i] = 0.f; }
    __syncthreads();
    for (int a = t; a < NA; a += 256) {
        unsigned bits = g_mining[b][a];
        if (!(bits >> 31) && (int)(bits >> 20) == bin0) {
            int sb = (bits >> 8) & 0xFFF;
            atomicAdd(&h1c[sb], 1u);
            atomicAdd(&h1s[sb], __uint_as_float(bits));
        }
    }
    __syncthreads();
    int bin1, krem1, all1; float above1;
    block_select(h1c, h1s, 4096, krem0, bin1, krem1, above1, all1);
    acc += above1;                                        // all1 impossible by invariant

    // pass 2: refine on low 8 bits
    if (t < 256) { h2c[t] = 0u; h2s[t] = 0.f; }
    __syncthreads();
    unsigned target = ((unsigned)bin0 << 12) | (unsigned)bin1;
    for (int a = t; a < NA; a += 256) {
        unsigned bits = g_mining[b][a];
        if (!(bits >> 31) && (bits >> 8) == target) {
            atomicAdd(&h2c[bits & 0xFF], 1u);
            atomicAdd(&h2s[bits & 0xFF], __uint_as_float(bits));
        }
    }
    __syncthreads();
    int bin2, krem2, all2; float above2;
    block_select(h2c, h2s, 256, krem1, bin2, krem2, above2, all2);
    if (t == 0) {
        if (all2) g_negSum[b] = acc + above2;             // defensive
        else {
            unsigned tb = ((unsigned)bin0 << 20) | ((unsigned)bin1 << 8) | (unsigned)bin2;
            g_negSum[b] = acc + above2 + (float)krem2 * __uint_as_float(tb);
        }
    }
}

__global__ void k_final(float* __restrict__ out) {
    if (threadIdx.x == 0 && blockIdx.x == 0) {
        int tp = 0; float ns = 0.f;
        for (int b = 0; b < NB; b++) { tp += g_numPosB[b]; ns += g_negSum[b]; }
        float np = fmaxf(1.f, (float)tp);
        out[0] = g_locSum / (np * 4.f);                 // localisation_loss
        out[1] = (g_posCe + ns) / (np * 4.f);           // classification_loss
    }
}

// ---------------- launch ----------------
extern "C" void kernel_launch(void* const* d_in, const int* in_sizes, int n_in,
                              void* d_out, int out_size)
{
    const float* conf    = (const float*)d_in[0];
    const float* pred    = (const float*)d_in[1];
    const float* gts     = (const float*)d_in[2];
    const int*   counts  = (const int*)d_in[3];
    const float* anchors = (const float*)d_in[4];
    float* out = (float*)d_out;

    k_zero   <<<1024, 256>>>();
    k_match  <<<dim3((NA + 255) / 256, NB), 256>>>(gts, counts, anchors);
    k_scatter<<<1, 32>>>(counts);
    k_main   <<<dim3(NA / (CHUNK * CPB), NB), 256>>>(conf, pred, gts, anchors);
    k_neg    <<<NB, 256>>>();
    k_final  <<<1, 32>>>(out);
    (void)in_sizes; (void)n_in; (void)out_size;
}

// round 9
// speedup vs baseline: 1.4328x; 1.4328x over previous
#include <cuda_runtime.h>
#include <cstdint>
#include <math_constants.h>

#define NB 16
#define NA 65472
#define NC 81
#define NG 50
#define NSLICE 8
#define BETA_C (1.0f/9.0f)
#define CHUNK 64                      // anchors per pipeline chunk
#define CPB 11                        // chunks per block; 1023 = 11*93
#define CHUNK_FLOATS (CHUNK*NC)       // 5184 floats = 20736 B
#define CHUNK_VEC (CHUNK_FLOATS/4)    // 1296 float4

// ---------------- scratch (static __device__, no allocation) ----------------
__device__ float              g_bestIou[NB][NA];
__device__ unsigned char      g_bestIdx[NB][NA];
__device__ unsigned long long g_gtBest[NB][NG];
__device__ unsigned           g_mining[NB][NA];     // float bits; sign bit => positive anchor
__device__ unsigned           g_h0cnt[NB][NSLICE][2048];
__device__ float              g_h0sum[NB][NSLICE][2048];
__device__ unsigned           g_h1cnt[NB][4096];
__device__ float              g_h1sum[NB][4096];
__device__ unsigned           g_h2cnt[NB][256];
__device__ float              g_h2sum[NB][256];
__device__ int                g_numPosB[NB];
__device__ float              g_posCe;
__device__ float              g_locSum;
__device__ float              g_negSum[NB];
__device__ int                g_done[NB];
__device__ int                g_b0[NB], g_k1[NB], g_b1[NB], g_k2[NB];

// ---------------- zero scratch (graph replays re-run this) ----------------
__global__ void k_zero() {
    int i = blockIdx.x * blockDim.x + threadIdx.x;   // 0 .. 262143
    ((unsigned*)g_h0cnt)[i] = 0u;
    ((float*)g_h0sum)[i]    = 0.f;
    if (i < NB * 4096) { ((unsigned*)g_h1cnt)[i] = 0u; ((float*)g_h1sum)[i] = 0.f; }
    if (i < NB * 256)  { ((unsigned*)g_h2cnt)[i] = 0u; ((float*)g_h2sum)[i] = 0.f; }
    if (i < NB * NG)   ((unsigned long long*)g_gtBest)[i] = 0ull;
    if (i < NB)        { g_numPosB[i] = 0; g_negSum[i] = 0.f; g_done[i] = 0; }
    if (i == 0)        { g_posCe = 0.f; g_locSum = 0.f; }
}

// ---------------- matching: per-anchor best box + per-GT best anchor ----------------
__global__ __launch_bounds__(256) void k_match(
    const float* __restrict__ gts, const int* __restrict__ counts,
    const float* __restrict__ anchors)
{
    __shared__ float sbx0[NG], sby0[NG], sbx1[NG], sby1[NG], sba[NG];
    __shared__ unsigned long long sgt[NG];
    int b = blockIdx.y;
    int tid = threadIdx.x;
    if (tid < NG) {
        const float* g = gts + ((size_t)b * NG + tid) * 5;
        float x0 = g[0], y0 = g[1], x1 = g[2], y1 = g[3];
        sbx0[tid] = x0; sby0[tid] = y0; sbx1[tid] = x1; sby1[tid] = y1;
        sba[tid]  = (x1 - x0) * (y1 - y0);
        sgt[tid]  = 0ull;
    }
    __syncthreads();
    int count = counts[b];
    int a = blockIdx.x * blockDim.x + tid;
    bool valid = a < NA;
    float ax0 = 0, ay0 = 0, ax1 = 0, ay1 = 0, aarea = 0;
    if (valid) {
        const float* ap = anchors + (size_t)a * 4;
        ax0 = ap[0]; ay0 = ap[1]; ax1 = ap[2]; ay1 = ap[3];
        aarea = (ax1 - ax0) * (ay1 - ay0);
    }
    float best = -1.f; int bidx = 0;
    int lane = tid & 31;
    for (int g = 0; g < count; ++g) {
        float ltx = fmaxf(ax0, sbx0[g]), lty = fmaxf(ay0, sby0[g]);
        float rbx = fminf(ax1, sbx1[g]), rby = fminf(ay1, sby1[g]);
        float w = fmaxf(rbx - ltx, 0.f), h = fmaxf(rby - lty, 0.f);
        float inter = w * h;
        unsigned key = 0u;
        if (valid && inter > 0.f) {
            float iou = __fdividef(inter, aarea + sba[g] - inter + 1e-10f);
            if (iou > best) { best = iou; bidx = g; }
            key = __float_as_uint(iou);
        }
        unsigned wmax = __reduce_max_sync(0xffffffffu, key);
        if (wmax) {
            unsigned ball = __ballot_sync(0xffffffffu, key == wmax);
            if (lane == (__ffs(ball) - 1))
                atomicMax(&sgt[g], ((unsigned long long)wmax << 32) |
                                   (unsigned long long)(0xFFFFFFFFu - (unsigned)a));
        }
    }
    if (valid) {
        g_bestIou[b][a] = best;
        g_bestIdx[b][a] = (unsigned char)bidx;
    }
    __syncthreads();
    if (tid < count) atomicMax(&g_gtBest[b][tid], sgt[tid]);
}

// ---------------- forced scatter: each GT's best anchor becomes positive ----------------
__global__ void k_scatter(const int* __restrict__ counts) {
    int b = threadIdx.x;
    if (b >= NB) return;
    int count = counts[b];
    for (int g = 0; g < count; ++g) {   // ascending: last g wins on collision
        unsigned long long p = g_gtBest[b][g];
        unsigned a = p ? (0xFFFFFFFFu - (unsigned)(p & 0xFFFFFFFFull)) : 0u;
        g_bestIou[b][a] = 2.0f;
        g_bestIdx[b][a] = (unsigned char)g;
    }
}

// ---------------- main streaming pass: pipelined cp.async, 4 threads/anchor ----------------
__global__ __launch_bounds__(256) void k_main(
    const float* __restrict__ conf, const float* __restrict__ pred,
    const float* __restrict__ gts,  const float* __restrict__ anchors)
{
    __shared__ float sm[2][CHUNK_FLOATS];            // 2 * 20736 B
    __shared__ float s_posCe, s_loc;
    __shared__ int   s_np;
    int b = blockIdx.y;
    int t = threadIdx.x;
    int al = t >> 2, p = t & 3;                      // anchor-in-chunk, class partition
    if (t == 0) { s_posCe = 0.f; s_loc = 0.f; s_np = 0; }

    int chunk0 = blockIdx.x * CPB;
    const float* base = conf + (size_t)b * NA * NC;
    unsigned sbase = (unsigned)__cvta_generic_to_shared(&sm[0][0]);

    // preload chunk0 -> buf0
    {
        const float4* src = (const float4*)(base + (size_t)chunk0 * CHUNK_FLOATS);
        for (int j = t; j < CHUNK_VEC; j += 256)
            asm volatile("cp.async.cg.shared.global [%0], [%1], 16;"
                         :: "r"(sbase + j * 16), "l"(src + j));
        asm volatile("cp.async.commit_group;");
    }

    for (int i = 0; i < CPB; ++i) {
        int cur = i & 1;
        if (i + 1 < CPB) {
            const float4* src = (const float4*)(base + (size_t)(chunk0 + i + 1) * CHUNK_FLOATS);
            unsigned dst = sbase + (cur ^ 1) * (CHUNK_FLOATS * 4);
            for (int j = t; j < CHUNK_VEC; j += 256)
                asm volatile("cp.async.cg.shared.global [%0], [%1], 16;"
                             :: "r"(dst + j * 16), "l"(src + j));
            asm volatile("cp.async.commit_group;");
            asm volatile("cp.async.wait_group 1;");
        } else {
            asm volatile("cp.async.wait_group 0;");
        }
        __syncthreads();

        int c = chunk0 + i;
        const float* row = &sm[cur][al * NC];
        float x0 = 0.f, s = 0.f, s1 = 0.f;
        if (p == 0) { x0 = row[0]; s = __expf(x0); }
        const float* q = row + 1 + p * 20;
        #pragma unroll
        for (int j = 0; j < 20; j += 2) { s += __expf(q[j]); s1 += __expf(q[j + 1]); }
        s += s1;
        s += __shfl_xor_sync(0xffffffffu, s, 1);
        s += __shfl_xor_sync(0xffffffffu, s, 2);

        if (p == 0) {
            float lse = __logf(s);
            int a = c * CHUNK + al;
            float iou = g_bestIou[b][a];
            int   gi  = g_bestIdx[b][a];
            int label = 0;
            if (iou >= 0.5f) label = (int)gts[((size_t)b * NG + gi) * 5 + 4];
            if (label > 0) {
                float ce = lse - row[label];
                g_mining[b][a] = 0x80000000u;
                atomicAdd(&s_posCe, ce);
                atomicAdd(&s_np, 1);
                const float* gb = gts + ((size_t)b * NG + gi) * 5;
                float bx0 = gb[0], by0 = gb[1], bx1 = gb[2], by1 = gb[3];
                const float* ap = anchors + (size_t)a * 4;
                float ax0 = ap[0], ay0 = ap[1], ax1 = ap[2], ay1 = ap[3];
                float acx = (ax0 + ax1) * 0.5f, acy = (ay0 + ay1) * 0.5f;
                float aw = ax1 - ax0, ah = ay1 - ay0;
                float mcx = (bx0 + bx1) * 0.5f, mcy = (by0 + by1) * 0.5f;
                float mw = bx1 - bx0, mh = by1 - by0;
                float tt[4];
                tt[0] = (mcx - acx) / (aw * 0.1f);
                tt[1] = (mcy - acy) / (ah * 0.1f);
                tt[2] = logf(mw / aw + 1e-10f) / 0.2f;
                tt[3] = logf(mh / ah + 1e-10f) / 0.2f;
                const float* pp = pred + ((size_t)b * NA + a) * 4;
                float ls = 0.f;
                #pragma unroll
                for (int j = 0; j < 4; j++) {
                    float n = fabsf(pp[j] - tt[j]);
                    ls += (n < BETA_C) ? 0.5f * n * n * (1.f / BETA_C) : n - 0.5f * BETA_C;
                }
                atomicAdd(&s_loc, ls);
            } else {
                float mining = lse - x0;                 // = ce for class 0; > 0
                unsigned bits = __float_as_uint(mining);
                g_mining[b][a] = bits;
                int slice = (c ^ al) & (NSLICE - 1);
                atomicAdd(&g_h0cnt[b][slice][bits >> 20], 1u);
                atomicAdd(&g_h0sum[b][slice][bits >> 20], mining);
            }
        }
        __syncthreads();   // buffer `cur` may be overwritten next iteration
    }
    if (t == 0) {
        if (s_np)            atomicAdd(&g_numPosB[b], s_np);
        if (s_posCe != 0.f)  atomicAdd(&g_posCe, s_posCe);
        if (s_loc   != 0.f)  atomicAdd(&g_locSum, s_loc);
    }
}

// ---------------- block-wide radix-bin threshold finder ----------------
__device__ void block_select(const unsigned* cnt, const float* sum, int nbins, int k,
                             int& bin, int& krem, float& above, int& all)
{
    __shared__ unsigned sc[256];
    __shared__ float ss[256];
    __shared__ int rbin, rkrem, rall;
    __shared__ float rabove;
    int t = threadIdx.x;
    int per = nbins >> 8;
    int lo = t * per;
    unsigned ccnt = 0; float csum = 0.f;
    for (int i = 0; i < per; i++) { ccnt += cnt[lo + i]; csum += sum[lo + i]; }
    sc[t] = ccnt; ss[t] = csum;
    __syncthreads();
    for (int off = 1; off < 256; off <<= 1) {            // inclusive suffix scan
        unsigned cv = (t + off < 256) ? sc[t + off] : 0u;
        float sv    = (t + off < 256) ? ss[t + off] : 0.f;
        __syncthreads();
        sc[t] += cv; ss[t] += sv;
        __syncthreads();
    }
    if (t == 0) { rall = (sc[0] <= (unsigned)k); rabove = ss[0]; rbin = -1; rkrem = 0; }
    __syncthreads();
    if (!rall) {
        unsigned cabove = sc[t] - ccnt;                  // strictly above this chunk
        if (cabove <= (unsigned)k && cabove + ccnt > (unsigned)k) {
            unsigned run = cabove;
            float srun = ss[t] - csum;
            for (int bb = lo + per - 1; bb >= lo; --bb) {
                unsigned cb = cnt[bb];
                if (run + cb > (unsigned)k) { rbin = bb; rkrem = k - (int)run; rabove = srun; break; }
                run += cb; srun += sum[bb];
            }
        }
    }
    __syncthreads();
    bin = rbin; krem = rkrem; above = rabove; all = rall;
}

// ---------------- sel0: collapse h0 slices + level-0 select (per-batch block) ----------------
__global__ __launch_bounds__(256) void k_sel0() {
    int b = blockIdx.x;
    int t = threadIdx.x;
    for (int bin = t; bin < 2048; bin += 256) {
        unsigned c = 0; float s = 0.f;
        #pragma unroll
        for (int sl = 0; sl < NSLICE; ++sl) { c += g_h0cnt[b][sl][bin]; s += g_h0sum[b][sl][bin]; }
        g_h0cnt[b][0][bin] = c; g_h0sum[b][0][bin] = s;
    }
    __syncthreads();
    int k = 3 * g_numPosB[b];
    int bin, krem, all; float above;
    block_select(&g_h0cnt[b][0][0], &g_h0sum[b][0][0], 2048, k, bin, krem, above, all);
    if (t == 0) {
        if (k == 0)      { g_done[b] = 1; }                       // negSum stays 0
        else if (all)    { g_done[b] = 1; g_negSum[b] = above; }  // all negatives selected
        else             { g_b0[b] = bin; g_k1[b] = krem; g_negSum[b] = above; }
    }
}

__global__ __launch_bounds__(256) void k_pass1() {
    int b = blockIdx.y;
    if (g_done[b]) return;
    int a = blockIdx.x * blockDim.x + threadIdx.x;
    if (a >= NA) return;
    unsigned bits = g_mining[b][a];
    if (bits >> 31) return;
    if ((int)(bits >> 20) == g_b0[b]) {
        int sb = (bits >> 8) & 0xFFF;
        atomicAdd(&g_h1cnt[b][sb], 1u);
        atomicAdd(&g_h1sum[b][sb], __uint_as_float(bits));
    }
}

__global__ __launch_bounds__(256) void k_sel1() {
    int b = blockIdx.x;
    if (g_done[b]) return;
    int k = g_k1[b];
    int bin, krem, all; float above;
    block_select(&g_h1cnt[b][0], &g_h1sum[b][0], 4096, k, bin, krem, above, all);
    if (threadIdx.x == 0) {
        if (all) { g_done[b] = 1; g_negSum[b] += above; }   // cannot happen by invariant
        else     { g_b1[b] = bin; g_k2[b] = krem; g_negSum[b] += above; }
    }
}

__global__ __launch_bounds__(256) void k_pass2() {
    int b = blockIdx.y;
    if (g_done[b]) return;
    int a = blockIdx.x * blockDim.x + threadIdx.x;
    if (a >= NA) return;
    unsigned bits = g_mining[b][a];
    if (bits >> 31) return;
    unsigned target = ((unsigned)g_b0[b] << 12) | (unsigned)g_b1[b];
    if ((bits >> 8) == target) {
        atomicAdd(&g_h2cnt[b][bits & 0xFF], 1u);
        atomicAdd(&g_h2sum[b][bits & 0xFF], __uint_as_float(bits));
    }
}

__global__ __launch_bounds__(256) void k_sel2() {
    int b = blockIdx.x;
    if (g_done[b]) return;
    int k = g_k2[b];
    int bin, krem, all; float above;
    block_select(&g_h2cnt[b][0], &g_h2sum[b][0], 256, k, bin, krem, above, all);
    if (threadIdx.x == 0) {
        if (all) { g_negSum[b] += above; }
        else {
            unsigned tb = ((unsigned)g_b0[b] << 20) | ((unsigned)g_b1[b] << 8) | (unsigned)bin;
            float val = __uint_as_float(tb);        // all elements in this bin share exact bits
            g_negSum[b] += above + (float)krem * val;
        }
    }
}

__global__ void k_final(float* __restrict__ out) {
    if (threadIdx.x == 0 && blockIdx.x == 0) {
        int tp = 0; float ns = 0.f;
        for (int b = 0; b < NB; b++) { tp += g_numPosB[b]; ns += g_negSum[b]; }
        float np = fmaxf(1.f, (float)tp);
        out[0] = g_locSum / (np * 4.f);                 // localisation_loss
        out[1] = (g_posCe + ns) / (np * 4.f);           // classification_loss
    }
}

// ---------------- launch ----------------
extern "C" void kernel_launch(void* const* d_in, const int* in_sizes, int n_in,
                              void* d_out, int out_size)
{
    const float* conf    = (const float*)d_in[0];
    const float* pred    = (const float*)d_in[1];
    const float* gts     = (const float*)d_in[2];
    const int*   counts  = (const int*)d_in[3];
    const float* anchors = (const float*)d_in[4];
    float* out = (float*)d_out;

    k_zero   <<<1024, 256>>>();
    k_match  <<<dim3((NA + 255) / 256, NB), 256>>>(gts, counts, anchors);
    k_scatter<<<1, 32>>>(counts);
    k_main   <<<dim3(NA / (CHUNK * CPB), NB), 256>>>(conf, pred, gts, anchors);
    k_sel0   <<<NB, 256>>>();
    k_pass1  <<<dim3((NA + 255) / 256, NB), 256>>>();
    k_sel1   <<<NB, 256>>>();
    k_pass2  <<<dim3((NA + 255) / 256, NB), 256>>>();
    k_sel2   <<<NB, 256>>>();
    k_final  <<<1, 32>>>(out);
    (void)in_sizes; (void)n_in; (void)out_size;
}